// round 17
// baseline (speedup 1.0000x reference)
#include <cuda_runtime.h>
#include <math.h>

#define TT   500
#define BB   256
#define ENCN 700
#define HIDN 128
#define LCAP 128          // list capacity (u32 entries) per (b,t); mean firing 35
#define NTHD 32768        // BB*HIDN
#define TCH  125          // time-chunk length (4 chunks pipelined)
#define ZSENT (ENCN << 8) // sentinel byte-offset -> zero smem row (row stride 256 B)
#define GTHR 1024         // gather block threads (32 warps/SM, 1 block/SM)
#define NPRE 44           // prefetch entries (11 x uint4); P(n>44) ~ 6% -> tail loop

// ---------------- static device scratch (allocation-free rule) ----------------
__device__ float          g_w1t[ENCN * HIDN];               // w1 transposed [enc][hid]
__device__ int            g_cnt [BB * TT];                  // firing count per (b,t)
__device__ unsigned int   g_list[(size_t)BB * TT * LCAP];   // byte offsets e<<8, 4-padded
__device__ float          g_h   [(size_t)TT * BB * HIDN];   // layer-1 pre-filter activations
__device__ unsigned char  g_s1b [(size_t)TT * BB * HIDN];   // layer-1 spikes as bytes
__device__ float          g_o   [TT * BB];                  // layer-2 pre-filter input
__device__ float4         g_st1 [NTHD];                     // scan1 state (p1,q1,pr,qr) per (b,h)
__device__ float4         g_st2 [BB];                       // scan2 state per b

// Constants exactly as XLA-on-GPU computes them (bit-exact — DO NOT TOUCH):
__device__ __forceinline__ void snn_consts(float& d, float& cd1, float& cdr) {
    d        = expf(-0.05f);          // libdevice __nv_expf
    float e1 = expf(1.0f);
    float c1 = __fdiv_rn(e1, 20.0f);
    cd1      = __fmul_rn(c1, d);
    float cr = __fdiv_rn(__fmul_rn(-2.0f, e1), 20.0f);
    cdr      = __fmul_rn(cr, d);
}

// ptxas-contracted scan step (bit-exact — DO NOT TOUCH):
__device__ __forceinline__ void alpha_step(float d, float cd, float& p, float& q, float in) {
    q = fmaf(d, q, __fmul_rn(cd, p));
    p = fmaf(d, p, in);
}

// ---------------- K_t: transpose w1 [hid][enc] -> [enc][hid] ----------------
__global__ void k_transpose(const float* __restrict__ w1) {
    int i = blockIdx.x * blockDim.x + threadIdx.x;
    if (i < ENCN * HIDN) {
        int e = i >> 7;
        int h = i & (HIDN - 1);
        g_w1t[i] = w1[h * ENCN + e];
    }
}

// ---------------- K0: ballot-compact u32 byte-offsets, t-chunked, 4-padded ----------------
__global__ __launch_bounds__(256) void k_compact(const float* __restrict__ x, int t0) {
    int b    = blockIdx.y;
    int t    = t0 + blockIdx.x * 8 + (threadIdx.x >> 5);
    int lane = threadIdx.x & 31;
    if (t >= t0 + TCH) return;

    const float4* xr4 = (const float4*)(x + (size_t)b * (TT * ENCN) + (size_t)t * ENCN);

    float4 v[6];
#pragma unroll
    for (int g = 0; g < 6; ++g) {
        int idx = g * 32 + lane;                 // float4 index, 175 per row
        v[g] = (idx < 175) ? __ldg(xr4 + idx)
                           : make_float4(0.f, 0.f, 0.f, 0.f);
    }

    unsigned int* lst = g_list + ((size_t)b * TT + t) * LCAP;
    const unsigned lt = (1u << lane) - 1u;
    int cnt = 0;
#pragma unroll
    for (int g = 0; g < 6; ++g) {
        bool f0 = v[g].x > 0.5f, f1 = v[g].y > 0.5f, f2 = v[g].z > 0.5f, f3 = v[g].w > 0.5f;
        unsigned m0 = __ballot_sync(0xffffffffu, f0);
        unsigned m1 = __ballot_sync(0xffffffffu, f1);
        unsigned m2 = __ballot_sync(0xffffffffu, f2);
        unsigned m3 = __ballot_sync(0xffffffffu, f3);
        int p = cnt + __popc(m0 & lt) + __popc(m1 & lt) + __popc(m2 & lt) + __popc(m3 & lt);
        unsigned e0s = (unsigned)((g * 128 + lane * 4) << 8);   // byte offsets, row stride 256
        if (f0) { if (p < LCAP) lst[p] = e0s;         ++p; }
        if (f1) { if (p < LCAP) lst[p] = e0s + 256;   ++p; }
        if (f2) { if (p < LCAP) lst[p] = e0s + 512;   ++p; }
        if (f3) { if (p < LCAP) lst[p] = e0s + 768;   ++p; }
        cnt += __popc(m0) + __popc(m1) + __popc(m2) + __popc(m3);
    }
    cnt = cnt < LCAP ? cnt : LCAP;
    // sentinel-pad [cnt, ceil4(cnt)) (<=3 entries) so gather groups are branch-free
    int padEnd = (cnt + 3) & ~3;
    if (padEnd > NPRE) padEnd = NPRE;            // entries beyond 44 handled by tail loop
    for (int i = cnt + lane; i < padEnd; i += 32) lst[i] = (unsigned)ZSENT;
    if (lane == 0) g_cnt[b * TT + t] = cnt;
}

// ---------------- K_A: sparse gather GEMM, t-chunked, 64-wide LDS.64, 32 warps/SM ----------------
// grid (BB, 2), 1024 thr, 1 block/SM. Warp-per-t stride 32 over this t-chunk.
// Sentinel row 700 = zeros (+0.0f exact); ascending-e serial order per column.
__global__ __launch_bounds__(GTHR, 1) void k_gather(int t0) {
    extern __shared__ float w1s[];   // [701][64] = 179456 B (row 700 = zeros)
    const int b = blockIdx.x, hh = blockIdx.y;
    const int tid  = threadIdx.x;
    const int wid  = tid >> 5;       // 0..31
    const int lane = tid & 31;

    for (int i = tid; i < (ENCN + 1) * 64; i += GTHR) {
        int e = i >> 6, h = i & 63;
        w1s[i] = (e < ENCN) ? g_w1t[e * HIDN + hh * 64 + h] : 0.0f;
    }
    __syncthreads();

    const char* wbase = (const char*)w1s + lane * 8;   // per-thread column pair base

    for (int t = t0 + wid; t < t0 + TCH; t += 32) {
        const int base = b * TT + t;
        const int n = __ldg(g_cnt + base);
        const uint4* l4 = (const uint4*)(g_list + (size_t)base * LCAP);

        // unconditional 11 x LDG.128 prefetch (44 entries; MLP=11)
        uint4 v[11];
#pragma unroll
        for (int r = 0; r < 11; ++r) v[r] = __ldg(l4 + r);

        const int ng = ((n < NPRE ? n : NPRE) + 3) >> 2;   // groups of 4 (= 1 uint4)
        float a0 = 0.0f, a1 = 0.0f;
#pragma unroll
        for (int g = 0; g < 11; ++g) {
            if (g < ng) {
                float2 w0 = *(const float2*)(wbase + v[g].x);
                float2 w1v = *(const float2*)(wbase + v[g].y);
                float2 w2v = *(const float2*)(wbase + v[g].z);
                float2 w3v = *(const float2*)(wbase + v[g].w);
                a0 = __fadd_rn(a0, w0.x);  a1 = __fadd_rn(a1, w0.y);
                a0 = __fadd_rn(a0, w1v.x); a1 = __fadd_rn(a1, w1v.y);
                a0 = __fadd_rn(a0, w2v.x); a1 = __fadd_rn(a1, w2v.y);
                a0 = __fadd_rn(a0, w3v.x); a1 = __fadd_rn(a1, w3v.y);
            }
        }
        // rare tail (P ~ 6%): entries 44..n-1, still ascending
        if (n > NPRE) {
            const unsigned int* lst = g_list + (size_t)base * LCAP;
            for (int k = NPRE; k < n; ++k) {
                float2 w = *(const float2*)(wbase + __ldg(lst + k));
                a0 = __fadd_rn(a0, w.x);
                a1 = __fadd_rn(a1, w.y);
            }
        }

        float2* outp = (float2*)(g_h + (size_t)t * NTHD + b * HIDN + hh * 64 + lane * 2);
        *outp = make_float2(a0, a1);
    }
}

// ---------------- K_B: layer-1 scan, t-chunked with state checkpointing ----------------
// 25 batches of 5 t's, 4-deep rotating prefetch. State (p1,q1,pr,qr) carried in g_st1.
__global__ __launch_bounds__(256, 1) void k_scan1(int t0) {
    int gid = blockIdx.x * 256 + threadIdx.x;   // b*128 + h

    float d, cd1, cdr;
    snn_consts(d, cd1, cdr);

    float p1, q1, pr, qr;
    if (t0 == 0) { p1 = q1 = pr = qr = 0.0f; }
    else { float4 st = g_st1[gid]; p1 = st.x; q1 = st.y; pr = st.z; qr = st.w; }

    float buf[4][5];
#pragma unroll
    for (int k = 0; k < 4; ++k)
#pragma unroll
        for (int j = 0; j < 5; ++j)
            buf[k][j] = __ldg(&g_h[(size_t)(t0 + k * 5 + j) * NTHD + gid]);

    for (int bi4 = 0; bi4 < 25; bi4 += 4) {
#pragma unroll
        for (int s = 0; s < 4; ++s) {
            int bi = bi4 + s;
            if (bi < 25) {
                int tb = t0 + bi * 5;
#pragma unroll
                for (int j = 0; j < 5; ++j) {
                    alpha_step(d, cd1, p1, q1, buf[s][j]);
                    qr = fmaf(d, qr, __fmul_rn(cdr, pr));
                    float u = __fadd_rn(q1, qr);
                    float sv = (u >= 1.0f) ? 1.0f : 0.0f;
                    pr = fmaf(d, pr, sv);
                    g_s1b[(size_t)(tb + j) * NTHD + gid] = (unsigned char)(u >= 1.0f);
                }
                int nb = bi + 4;
                if (nb < 25) {
#pragma unroll
                    for (int j = 0; j < 5; ++j)
                        buf[s][j] = __ldg(&g_h[(size_t)(t0 + nb * 5 + j) * NTHD + gid]);
                }
            }
        }
    }

    g_st1[gid] = make_float4(p1, q1, pr, qr);
}

// ---------------- K_C: o[t,b] = serial ascending-h FFMA over byte spikes, t-chunked ----------------
__global__ __launch_bounds__(256) void k_dot2(const float* __restrict__ w2, int t0) {
    __shared__ float w2s[HIDN];
    if (threadIdx.x < HIDN) w2s[threadIdx.x] = w2[threadIdx.x];
    __syncthreads();

    int t = t0 + blockIdx.x;
    int b = threadIdx.x;
    const uint4* sp = (const uint4*)(g_s1b + (size_t)t * NTHD + b * HIDN);

    float acc = 0.0f;
#pragma unroll
    for (int j = 0; j < 8; ++j) {
        uint4 v = __ldg(sp + j);
        unsigned wrd[4] = { v.x, v.y, v.z, v.w };
#pragma unroll
        for (int k = 0; k < 4; ++k) {
            unsigned w = wrd[k];
            int base = j * 16 + k * 4;
            acc = fmaf((float)(w & 0xffu),         w2s[base + 0], acc);
            acc = fmaf((float)((w >> 8) & 0xffu),  w2s[base + 1], acc);
            acc = fmaf((float)((w >> 16) & 0xffu), w2s[base + 2], acc);
            acc = fmaf((float)(w >> 24),           w2s[base + 3], acc);
        }
    }
    g_o[t * BB + b] = acc;
}

// ---------------- K_D: layer-2 scan, t-chunked with state checkpointing ----------------
__global__ __launch_bounds__(BB, 1) void k_scan2(float* __restrict__ out, int t0) {
    int b = threadIdx.x;

    float d, cd1, cdr;
    snn_consts(d, cd1, cdr);

    float p2, q2, pr2, qr2;
    if (t0 == 0) { p2 = q2 = pr2 = qr2 = 0.0f; }
    else { float4 st = g_st2[b]; p2 = st.x; q2 = st.y; pr2 = st.z; qr2 = st.w; }

    float buf[4][5];
#pragma unroll
    for (int k = 0; k < 4; ++k)
#pragma unroll
        for (int j = 0; j < 5; ++j)
            buf[k][j] = __ldg(&g_o[(t0 + k * 5 + j) * BB + b]);

    for (int bi4 = 0; bi4 < 25; bi4 += 4) {
#pragma unroll
        for (int s = 0; s < 4; ++s) {
            int bi = bi4 + s;
            if (bi < 25) {
                int tb = t0 + bi * 5;
#pragma unroll
                for (int j = 0; j < 5; ++j) {
                    alpha_step(d, cd1, p2, q2, buf[s][j]);
                    qr2 = fmaf(d, qr2, __fmul_rn(cdr, pr2));
                    float u = __fadd_rn(q2, qr2);
                    float sv = (u >= 1.0f) ? 1.0f : 0.0f;
                    pr2 = fmaf(d, pr2, sv);
                    out[b * TT + (tb + j)] = sv;
                }
                int nb = bi + 4;
                if (nb < 25) {
#pragma unroll
                    for (int j = 0; j < 5; ++j)
                        buf[s][j] = __ldg(&g_o[(t0 + nb * 5 + j) * BB + b]);
                }
            }
        }
    }

    g_st2[b] = make_float4(p2, q2, pr2, qr2);
}

// ---------------- launch: time-chunked 3-stage pipeline on 3 streams ----------------
// Scans checkpoint their recurrence state between t-chunks (bit-exact), so each
// chunk's scan chain hides under the next chunk's gather.
extern "C" void kernel_launch(void* const* d_in, const int* in_sizes, int n_in,
                              void* d_out, int out_size) {
    const float* x = nullptr, *w1 = nullptr, *w2 = nullptr;
    for (int i = 0; i < n_in; ++i) {
        if      (in_sizes[i] == BB * TT * ENCN) x  = (const float*)d_in[i];
        else if (in_sizes[i] == HIDN * ENCN)    w1 = (const float*)d_in[i];
        else if (in_sizes[i] == HIDN)           w2 = (const float*)d_in[i];
    }

    static cudaStream_t sC = 0, sG = 0, sS = 0;
    static cudaEvent_t  evFork, evC[4], evG[4], evS;
    static int inited = 0;
    if (!inited) {
        cudaFuncSetAttribute(k_gather, cudaFuncAttributeMaxDynamicSharedMemorySize,
                             (ENCN + 1) * 64 * (int)sizeof(float));
        cudaStreamCreateWithFlags(&sC, cudaStreamNonBlocking);
        cudaStreamCreateWithFlags(&sG, cudaStreamNonBlocking);
        cudaStreamCreateWithFlags(&sS, cudaStreamNonBlocking);
        cudaEventCreateWithFlags(&evFork, cudaEventDisableTiming);
        cudaEventCreateWithFlags(&evS,    cudaEventDisableTiming);
        for (int i = 0; i < 4; ++i) {
            cudaEventCreateWithFlags(&evC[i], cudaEventDisableTiming);
            cudaEventCreateWithFlags(&evG[i], cudaEventDisableTiming);
        }
        inited = 1;
    }

    cudaEventRecord(evFork, 0);
    cudaStreamWaitEvent(sC, evFork, 0);
    cudaStreamWaitEvent(sG, evFork, 0);

    const int GSM = (ENCN + 1) * 64 * (int)sizeof(float);

    // launch #1..#4: T, C0, C1, G0  -> ncu captures G0
    k_transpose<<<(ENCN * HIDN + 255) / 256, 256, 0, sG>>>(w1);
    k_compact<<<dim3(16, BB), 256, 0, sC>>>(x, 0 * TCH);
    cudaEventRecord(evC[0], sC);
    k_compact<<<dim3(16, BB), 256, 0, sC>>>(x, 1 * TCH);
    cudaEventRecord(evC[1], sC);
    cudaStreamWaitEvent(sG, evC[0], 0);
    k_gather<<<dim3(BB, 2), GTHR, GSM, sG>>>(0 * TCH);
    cudaEventRecord(evG[0], sG);

    // chunk-0 scans (hide under G1)
    cudaStreamWaitEvent(sS, evG[0], 0);
    k_scan1<<<NTHD / 256, 256, 0, sS>>>(0 * TCH);
    k_dot2<<<TCH, BB, 0, sS>>>(w2, 0 * TCH);
    k_scan2<<<1, BB, 0, sS>>>((float*)d_out, 0 * TCH);

    k_compact<<<dim3(16, BB), 256, 0, sC>>>(x, 2 * TCH);
    cudaEventRecord(evC[2], sC);
    cudaStreamWaitEvent(sG, evC[1], 0);
    k_gather<<<dim3(BB, 2), GTHR, GSM, sG>>>(1 * TCH);
    cudaEventRecord(evG[1], sG);

    cudaStreamWaitEvent(sS, evG[1], 0);
    k_scan1<<<NTHD / 256, 256, 0, sS>>>(1 * TCH);
    k_dot2<<<TCH, BB, 0, sS>>>(w2, 1 * TCH);
    k_scan2<<<1, BB, 0, sS>>>((float*)d_out, 1 * TCH);

    k_compact<<<dim3(16, BB), 256, 0, sC>>>(x, 3 * TCH);
    cudaEventRecord(evC[3], sC);
    cudaStreamWaitEvent(sG, evC[2], 0);
    k_gather<<<dim3(BB, 2), GTHR, GSM, sG>>>(2 * TCH);
    cudaEventRecord(evG[2], sG);

    cudaStreamWaitEvent(sS, evG[2], 0);
    k_scan1<<<NTHD / 256, 256, 0, sS>>>(2 * TCH);
    k_dot2<<<TCH, BB, 0, sS>>>(w2, 2 * TCH);
    k_scan2<<<1, BB, 0, sS>>>((float*)d_out, 2 * TCH);

    cudaStreamWaitEvent(sG, evC[3], 0);
    k_gather<<<dim3(BB, 2), GTHR, GSM, sG>>>(3 * TCH);
    cudaEventRecord(evG[3], sG);

    cudaStreamWaitEvent(sS, evG[3], 0);
    k_scan1<<<NTHD / 256, 256, 0, sS>>>(3 * TCH);
    k_dot2<<<TCH, BB, 0, sS>>>(w2, 3 * TCH);
    k_scan2<<<1, BB, 0, sS>>>((float*)d_out, 3 * TCH);

    cudaEventRecord(evS, sS);
    cudaStreamWaitEvent(0, evS, 0);
}